// round 8
// baseline (speedup 1.0000x reference)
#include <cuda_runtime.h>
#include <math.h>

#define NN 100000
#define NE 3200000
#define INF_ 128
#define F1 32
#define F2 16

typedef unsigned long long ull;

// ---------------- scratch (static device globals; zero-init at module load) ----------------
__device__ float g_dinv[NN];          // weighted-deg accumulator -> rsqrt(deg+1)
__device__ int   g_cnt[NN];           // in-degree counts (persist through aggs)
__device__ int   g_row[NN];           // CSR row start (arrival-order block offsets)
__device__ int   g_rank[NE];          // per-edge rank within dst row
__device__ int2  g_cedge[NE];         // (src, norm-as-int-bits) per CSR slot
__device__ float g_h1[NN * F1];       // x @ W1
__device__ float g_hrelu[NN * F1];    // relu(layer1 out)
__device__ float g_h2[NN * F2];       // hrelu @ W2
__device__ int   g_total;             // running block-offset counter (reset in tail)

#define G1_BLOCKS 391                 // gemm1 blocks (256 thr, 1 node/thr)
#define GE_BLOCKS 12500               // edge blocks (256 thr)
#define NB 391                        // node blocks of 256

// ---------------- f32x2 packed-FMA helpers (sm_103a FFMA2) ----------------
__device__ __forceinline__ ull pack2(float a, float b) {
    ull r; asm("mov.b64 %0, {%1, %2};" : "=l"(r) : "f"(a), "f"(b)); return r;
}
__device__ __forceinline__ ull fma2(ull a, ull b, ull c) {
    ull d; asm("fma.rn.f32x2 %0, %1, %2, %3;" : "=l"(d) : "l"(a), "l"(b), "l"(c)); return d;
}
__device__ __forceinline__ float2 unpack2(ull v) {
    float x, y; asm("mov.b64 {%0, %1}, %2;" : "=f"(x), "=f"(y) : "l"(v));
    return make_float2(x, y);
}

// ---------------- fat kernel: gemm1 (bid < G1_BLOCKS) + count-with-rank ----------------
__global__ void __launch_bounds__(256) k_gemm1_count(
        const float* __restrict__ x, const float* __restrict__ W1,
        const int* __restrict__ ei, const float* __restrict__ ew) {
    __shared__ __align__(16) float sW[INF_ * F1];   // 16 KB (gemm path only)
    int bid = blockIdx.x;
    int tid = threadIdx.x;
    if (bid < G1_BLOCKS) {
        // ---- h1 = x @ W1 : thread-per-node, FFMA2 with LDS.128 W loads ----
        for (int i = tid; i < INF_ * F1; i += blockDim.x) sW[i] = W1[i];
        __syncthreads();
        int n = bid * 256 + tid;
        if (n >= NN) return;
        ull acc[F1 / 2];
#pragma unroll
        for (int j = 0; j < F1 / 2; j++) acc[j] = 0ull;
        const float4* xr = (const float4*)(x + (size_t)n * INF_);
        const float4* sW4 = (const float4*)sW;
        for (int k4 = 0; k4 < INF_ / 4; k4++) {
            float4 xv = xr[k4];
            float xs[4] = {xv.x, xv.y, xv.z, xv.w};
#pragma unroll
            for (int kk = 0; kk < 4; kk++) {
                ull xp = pack2(xs[kk], xs[kk]);
                const float4* wrow = sW4 + (k4 * 4 + kk) * (F1 / 4);
#pragma unroll
                for (int j4 = 0; j4 < F1 / 4; j4++) {
                    float4 w = wrow[j4];                     // one LDS.128
                    acc[2 * j4]     = fma2(xp, pack2(w.x, w.y), acc[2 * j4]);
                    acc[2 * j4 + 1] = fma2(xp, pack2(w.z, w.w), acc[2 * j4 + 1]);
                }
            }
        }
        float2* o = (float2*)(g_h1 + (size_t)n * F1);
#pragma unroll
        for (int j = 0; j < F1 / 2; j++) o[j] = unpack2(acc[j]);
    } else {
        // ---- per edge: count (rank recorded) + fp weighted degree at dst ----
        int e = (bid - G1_BLOCKS) * 256 + tid;
        if (e >= NE) return;
        int d = ei[NE + e];
        int r = atomicAdd(&g_cnt[d], 1);
        g_rank[e] = r;
        atomicAdd(&g_dinv[d], ew[e]);
    }
}

// ---- one-kernel scan: block sum -> arrival-order offset -> local exclusive scan ----
// row regions are disjoint (not monotone); lengths come from g_cnt. Also finalizes dinv.
__global__ void k_scanA() {
    __shared__ int sh[256];
    __shared__ int s_off;
    int t = threadIdx.x;
    int i = blockIdx.x * 256 + t;
    int v = (i < NN) ? g_cnt[i] : 0;
    sh[t] = v;
    __syncthreads();
    for (int off = 1; off < 256; off <<= 1) {
        int u = (t >= off) ? sh[t - off] : 0;
        __syncthreads();
        sh[t] += u;
        __syncthreads();
    }
    if (t == 255) s_off = atomicAdd(&g_total, sh[255]);
    __syncthreads();
    if (i < NN) {
        g_row[i] = s_off + sh[t] - v;   // exclusive start of node i's region
        g_dinv[i] = rsqrtf(g_dinv[i] + 1.0f);
    }
}

// per edge: norm = dinv[s]*ew*dinv[d]; write to row[d]+rank[e] — NO atomic
__global__ void k_scatter(const int* __restrict__ ei, const float* __restrict__ ew) {
    int e = blockIdx.x * blockDim.x + threadIdx.x;
    if (e >= NE) return;
    int s = ei[e];
    int d = ei[NE + e];
    float nrm = g_dinv[s] * ew[e] * g_dinv[d];
    int pos = g_row[d] + g_rank[e];
    g_cedge[pos] = make_int2(s, __float_as_int(nrm));
}

// layer1 aggregation: warp-per-node, HALF-warp per edge, float2 per lane.
__global__ void k_agg1(const float* __restrict__ b1) {
    const unsigned FULL = 0xffffffffu;
    int lane = threadIdx.x & 31;
    int n = blockIdx.x * (blockDim.x >> 5) + (threadIdx.x >> 5);
    if (n >= NN) return;
    int f2 = lane & 15;
    int half = lane >> 4;
    int beg = g_row[n];
    int end = beg + g_cnt[n];
    float ax0 = 0.f, ay0 = 0.f, ax1 = 0.f, ay1 = 0.f;
    int i = beg + half;
    for (; i + 6 < end; i += 8) {
        int2 e0 = g_cedge[i + 0];
        int2 e1 = g_cedge[i + 2];
        int2 e2 = g_cedge[i + 4];
        int2 e3 = g_cedge[i + 6];
        float2 h0 = *(const float2*)(g_h1 + (unsigned)e0.x * F1 + 2 * f2);
        float2 h1 = *(const float2*)(g_h1 + (unsigned)e1.x * F1 + 2 * f2);
        float2 h2 = *(const float2*)(g_h1 + (unsigned)e2.x * F1 + 2 * f2);
        float2 h3 = *(const float2*)(g_h1 + (unsigned)e3.x * F1 + 2 * f2);
        float w0 = __int_as_float(e0.y), w1 = __int_as_float(e1.y);
        float w2 = __int_as_float(e2.y), w3 = __int_as_float(e3.y);
        ax0 += w0 * h0.x; ay0 += w0 * h0.y;
        ax1 += w1 * h1.x; ay1 += w1 * h1.y;
        ax0 += w2 * h2.x; ay0 += w2 * h2.y;
        ax1 += w3 * h3.x; ay1 += w3 * h3.y;
    }
    for (; i < end; i += 2) {
        int2 e0 = g_cedge[i];
        float2 h0 = *(const float2*)(g_h1 + (unsigned)e0.x * F1 + 2 * f2);
        float w0 = __int_as_float(e0.y);
        ax0 += w0 * h0.x; ay0 += w0 * h0.y;
    }
    float ax = ax0 + ax1, ay = ay0 + ay1;
    ax += __shfl_down_sync(FULL, ax, 16);
    ay += __shfl_down_sync(FULL, ay, 16);
    float di = g_dinv[n];
    float d2 = di * di;
    float2 hs = *(const float2*)(g_h1 + (unsigned)n * F1 + 2 * f2);
    float x1 = ax + d2 * hs.x + b1[2 * f2];
    float y1 = ay + d2 * hs.y + b1[2 * f2 + 1];
    if (lane < 16)
        *(float2*)(g_hrelu + (unsigned)n * F1 + 2 * f2) =
            make_float2(fmaxf(x1, 0.f), fmaxf(y1, 0.f));
}

// h2 = hrelu @ W2 thread-per-node, FFMA2 with LDS.128
__global__ void k_gemm2(const float* __restrict__ W2) {
    __shared__ __align__(16) float sW[F1 * F2];   // 2 KB
    int tid = threadIdx.x;
    for (int i = tid; i < F1 * F2; i += blockDim.x) sW[i] = W2[i];
    __syncthreads();
    int n = blockIdx.x * blockDim.x + tid;
    if (n >= NN) return;
    ull acc[F2 / 2];
#pragma unroll
    for (int j = 0; j < F2 / 2; j++) acc[j] = 0ull;
    const float4* hr = (const float4*)(g_hrelu + (size_t)n * F1);
    const float4* sW4 = (const float4*)sW;
#pragma unroll
    for (int k4 = 0; k4 < F1 / 4; k4++) {
        float4 hv = hr[k4];
        float hs[4] = {hv.x, hv.y, hv.z, hv.w};
#pragma unroll
        for (int kk = 0; kk < 4; kk++) {
            ull hp = pack2(hs[kk], hs[kk]);
            const float4* wrow = sW4 + (k4 * 4 + kk) * (F2 / 4);
#pragma unroll
            for (int j4 = 0; j4 < F2 / 4; j4++) {
                float4 w = wrow[j4];
                acc[2 * j4]     = fma2(hp, pack2(w.x, w.y), acc[2 * j4]);
                acc[2 * j4 + 1] = fma2(hp, pack2(w.z, w.w), acc[2 * j4 + 1]);
            }
        }
    }
    float2* o = (float2*)(g_h2 + (size_t)n * F2);
#pragma unroll
    for (int j = 0; j < F2 / 2; j++) o[j] = unpack2(acc[j]);
}

// layer2 aggregation + FC head + tail zeroing; warp-per-node, QUARTER-warp per edge.
__global__ void k_agg2_final(const float* __restrict__ b2,
                             const float* __restrict__ fc1_w, const float* __restrict__ fc1_b,
                             const float* __restrict__ fc2_w, const float* __restrict__ fc2_b,
                             float* __restrict__ out) {
    const unsigned FULL = 0xffffffffu;
    int lane = threadIdx.x & 31;
    int n = blockIdx.x * (blockDim.x >> 5) + (threadIdx.x >> 5);
    if (n >= NN) return;
    int qtr = lane >> 3;
    int f2 = lane & 7;
    int beg = g_row[n];
    int cnt = g_cnt[n];
    int end = beg + cnt;
    float ax0 = 0.f, ay0 = 0.f, ax1 = 0.f, ay1 = 0.f;
    int i = beg + qtr;
    for (; i + 4 < end; i += 8) {
        int2 e0 = g_cedge[i + 0];
        int2 e1 = g_cedge[i + 4];
        float2 h0 = *(const float2*)(g_h2 + (unsigned)e0.x * F2 + 2 * f2);
        float2 h1 = *(const float2*)(g_h2 + (unsigned)e1.x * F2 + 2 * f2);
        float w0 = __int_as_float(e0.y), w1 = __int_as_float(e1.y);
        ax0 += w0 * h0.x; ay0 += w0 * h0.y;
        ax1 += w1 * h1.x; ay1 += w1 * h1.y;
    }
    for (; i < end; i += 4) {
        int2 e0 = g_cedge[i];
        float2 h0 = *(const float2*)(g_h2 + (unsigned)e0.x * F2 + 2 * f2);
        float w0 = __int_as_float(e0.y);
        ax0 += w0 * h0.x; ay0 += w0 * h0.y;
    }
    float ax = ax0 + ax1, ay = ay0 + ay1;
    ax += __shfl_down_sync(FULL, ax, 16);
    ay += __shfl_down_sync(FULL, ay, 16);
    ax += __shfl_down_sync(FULL, ax, 8);
    ay += __shfl_down_sync(FULL, ay, 8);      // lanes 0..7 hold full sums
    float di = g_dinv[n];
    float d2 = di * di;
    float2 hs = *(const float2*)(g_h2 + (unsigned)n * F2 + 2 * f2);
    float x2x = ax + d2 * hs.x + b2[2 * f2];
    float x2y = ay + d2 * hs.y + b2[2 * f2 + 1];
    float p = x2x * fc1_w[2 * f2] + x2y * fc1_w[2 * f2 + 1];
    p += __shfl_xor_sync(FULL, p, 4);
    p += __shfl_xor_sync(FULL, p, 2);
    p += __shfl_xor_sync(FULL, p, 1);         // lanes 0..7 correct
    float x1f = p + fc1_b[0];
    float c = 1.0f / (1.0f + expf(-x1f));
    float qv = g_hrelu[(unsigned)n * F1 + lane] * fc2_w[lane];
#pragma unroll
    for (int off = 16; off >= 1; off >>= 1) qv += __shfl_xor_sync(FULL, qv, off);
    float r = qv + c * fc2_w[32] + fc2_b[0];
    if (lane == 0) {
        out[n] = r;
        out[NN + n] = x1f;
    }
    // tail zeroing for the NEXT replay (values already consumed above)
    if (lane == 1) g_cnt[n] = 0;
    if (lane == 2) g_dinv[n] = 0.0f;
    if (n == 0 && lane == 3) g_total = 0;
}

// ---------------- launch ----------------
extern "C" void kernel_launch(void* const* d_in, const int* in_sizes, int n_in,
                              void* d_out, int out_size) {
    const float* x     = (const float*)d_in[0];
    const int*   ei    = (const int*)  d_in[1];
    const float* ew    = (const float*)d_in[2];
    const float* W1    = (const float*)d_in[3];
    const float* b1    = (const float*)d_in[4];
    const float* W2    = (const float*)d_in[5];
    const float* b2    = (const float*)d_in[6];
    const float* fc1w  = (const float*)d_in[7];
    const float* fc1b  = (const float*)d_in[8];
    const float* fc2w  = (const float*)d_in[9];
    const float* fc2b  = (const float*)d_in[10];
    float* out = (float*)d_out;

    const int TB = 256;
    const int gW = (NN * 32 + TB - 1) / TB;   // warp-per-node: 8 nodes/block
    (void)in_sizes; (void)n_in; (void)out_size;

    k_gemm1_count<<<G1_BLOCKS + GE_BLOCKS, TB>>>(x, W1, ei, ew);   // 1
    k_scanA<<<NB, 256>>>();                                        // 2
    k_scatter<<<GE_BLOCKS, TB>>>(ei, ew);                          // 3
    k_agg1<<<gW, TB>>>(b1);                                        // 4 -> profiled slot
    k_gemm2<<<NB, TB>>>(W2);                                       // 5
    k_agg2_final<<<gW, TB>>>(b2, fc1w, fc1b, fc2w, fc2b, out);     // 6
}

// round 9
// speedup vs baseline: 1.0087x; 1.0087x over previous
#include <cuda_runtime.h>
#include <math.h>

#define NN 100000
#define NE 3200000
#define INF_ 128
#define F1 32
#define F2 16

typedef unsigned long long ull;

// ---------------- scratch (static device globals; zero-init at module load) ----------------
__device__ float g_dinv[NN];          // weighted-deg accumulator -> rsqrt(deg+1)
__device__ int   g_cnt[NN];           // in-degree counts (persist through aggs)
__device__ int   g_row[NN];           // CSR row start (arrival-order block offsets)
__device__ int   g_cur[NN];           // scatter cursors
__device__ int2  g_cedge[NE];         // (src, norm-as-int-bits) per CSR slot
__device__ float g_h1[NN * F1];       // x @ W1
__device__ float g_hrelu[NN * F1];    // relu(layer1 out)
__device__ float g_h2[NN * F2];       // hrelu @ W2
__device__ int   g_total;             // running block-offset counter (reset in tail)

#define G1_BLOCKS 391                 // gemm1 blocks (256 thr, 1 node/thr)
#define E4_BLOCKS 3125                // edge blocks (256 thr, 4 edges/thr)
#define NB 391                        // node blocks of 256

// ---------------- f32x2 packed-FMA helpers (sm_103a FFMA2) ----------------
__device__ __forceinline__ ull pack2(float a, float b) {
    ull r; asm("mov.b64 %0, {%1, %2};" : "=l"(r) : "f"(a), "f"(b)); return r;
}
__device__ __forceinline__ ull fma2(ull a, ull b, ull c) {
    ull d; asm("fma.rn.f32x2 %0, %1, %2, %3;" : "=l"(d) : "l"(a), "l"(b), "l"(c)); return d;
}
__device__ __forceinline__ float2 unpack2(ull v) {
    float x, y; asm("mov.b64 {%0, %1}, %2;" : "=f"(x), "=f"(y) : "l"(v));
    return make_float2(x, y);
}

// ---------------- fat kernel: gemm1 (bid < G1_BLOCKS) + batched count ----------------
__global__ void __launch_bounds__(256) k_gemm1_count(
        const float* __restrict__ x, const float* __restrict__ W1,
        const int* __restrict__ ei, const float* __restrict__ ew) {
    __shared__ __align__(16) float sW[INF_ * F1];   // 16 KB (gemm path only)
    int bid = blockIdx.x;
    int tid = threadIdx.x;
    if (bid < G1_BLOCKS) {
        // ---- h1 = x @ W1 : thread-per-node, FFMA2 with LDS.128 W loads ----
        for (int i = tid; i < INF_ * F1; i += blockDim.x) sW[i] = W1[i];
        __syncthreads();
        int n = bid * 256 + tid;
        if (n >= NN) return;
        ull acc[F1 / 2];
#pragma unroll
        for (int j = 0; j < F1 / 2; j++) acc[j] = 0ull;
        const float4* xr = (const float4*)(x + (size_t)n * INF_);
        const float4* sW4 = (const float4*)sW;
        for (int k4 = 0; k4 < INF_ / 4; k4++) {
            float4 xv = xr[k4];
            float xs[4] = {xv.x, xv.y, xv.z, xv.w};
#pragma unroll
            for (int kk = 0; kk < 4; kk++) {
                ull xp = pack2(xs[kk], xs[kk]);
                const float4* wrow = sW4 + (k4 * 4 + kk) * (F1 / 4);
#pragma unroll
                for (int j4 = 0; j4 < F1 / 4; j4++) {
                    float4 w = wrow[j4];                     // one LDS.128
                    acc[2 * j4]     = fma2(xp, pack2(w.x, w.y), acc[2 * j4]);
                    acc[2 * j4 + 1] = fma2(xp, pack2(w.z, w.w), acc[2 * j4 + 1]);
                }
            }
        }
        float2* o = (float2*)(g_h1 + (size_t)n * F1);
#pragma unroll
        for (int j = 0; j < F1 / 2; j++) o[j] = unpack2(acc[j]);
    } else {
        // ---- 4 edges per thread: int count + fp weighted degree at dst (REDG) ----
        int e = ((bid - G1_BLOCKS) * 256 + tid) * 4;
        if (e >= NE) return;
        int4   d4 = *(const int4*)  (ei + NE + e);
        float4 w4 = *(const float4*)(ew + e);
        atomicAdd(&g_cnt[d4.x], 1);
        atomicAdd(&g_cnt[d4.y], 1);
        atomicAdd(&g_cnt[d4.z], 1);
        atomicAdd(&g_cnt[d4.w], 1);
        atomicAdd(&g_dinv[d4.x], w4.x);
        atomicAdd(&g_dinv[d4.y], w4.y);
        atomicAdd(&g_dinv[d4.z], w4.z);
        atomicAdd(&g_dinv[d4.w], w4.w);
    }
}

// ---- one-kernel scan: block sum -> arrival-order offset -> local exclusive scan ----
__global__ void k_scanA() {
    __shared__ int sh[256];
    __shared__ int s_off;
    int t = threadIdx.x;
    int i = blockIdx.x * 256 + t;
    int v = (i < NN) ? g_cnt[i] : 0;
    sh[t] = v;
    __syncthreads();
    for (int off = 1; off < 256; off <<= 1) {
        int u = (t >= off) ? sh[t - off] : 0;
        __syncthreads();
        sh[t] += u;
        __syncthreads();
    }
    if (t == 255) s_off = atomicAdd(&g_total, sh[255]);
    __syncthreads();
    if (i < NN) {
        int ex = s_off + sh[t] - v;     // exclusive start of node i's region
        g_row[i] = ex;
        g_cur[i] = ex;
        g_dinv[i] = rsqrtf(g_dinv[i] + 1.0f);
    }
}

// 4 edges per thread: norm = dinv[s]*ew*dinv[d]; cursor-atomic scatter into CSR
__global__ void k_scatter(const int* __restrict__ ei, const float* __restrict__ ew) {
    int e = (blockIdx.x * blockDim.x + threadIdx.x) * 4;
    if (e >= NE) return;
    int4   s4 = *(const int4*)  (ei + e);
    int4   d4 = *(const int4*)  (ei + NE + e);
    float4 w4 = *(const float4*)(ew + e);
    float is0 = g_dinv[s4.x], is1 = g_dinv[s4.y], is2 = g_dinv[s4.z], is3 = g_dinv[s4.w];
    float id0 = g_dinv[d4.x], id1 = g_dinv[d4.y], id2 = g_dinv[d4.z], id3 = g_dinv[d4.w];
    float n0 = is0 * w4.x * id0;
    float n1 = is1 * w4.y * id1;
    float n2 = is2 * w4.z * id2;
    float n3 = is3 * w4.w * id3;
    int p0 = atomicAdd(&g_cur[d4.x], 1);
    int p1 = atomicAdd(&g_cur[d4.y], 1);
    int p2 = atomicAdd(&g_cur[d4.z], 1);
    int p3 = atomicAdd(&g_cur[d4.w], 1);
    g_cedge[p0] = make_int2(s4.x, __float_as_int(n0));
    g_cedge[p1] = make_int2(s4.y, __float_as_int(n1));
    g_cedge[p2] = make_int2(s4.z, __float_as_int(n2));
    g_cedge[p3] = make_int2(s4.w, __float_as_int(n3));
}

// layer1 aggregation: warp-per-node, HALF-warp per edge, float2 per lane.
__global__ void k_agg1(const float* __restrict__ b1) {
    const unsigned FULL = 0xffffffffu;
    int lane = threadIdx.x & 31;
    int n = blockIdx.x * (blockDim.x >> 5) + (threadIdx.x >> 5);
    if (n >= NN) return;
    int f2 = lane & 15;
    int half = lane >> 4;
    int beg = g_row[n];
    int end = beg + g_cnt[n];
    float ax0 = 0.f, ay0 = 0.f, ax1 = 0.f, ay1 = 0.f;
    int i = beg + half;
    for (; i + 6 < end; i += 8) {
        int2 e0 = g_cedge[i + 0];
        int2 e1 = g_cedge[i + 2];
        int2 e2 = g_cedge[i + 4];
        int2 e3 = g_cedge[i + 6];
        float2 h0 = *(const float2*)(g_h1 + (unsigned)e0.x * F1 + 2 * f2);
        float2 h1 = *(const float2*)(g_h1 + (unsigned)e1.x * F1 + 2 * f2);
        float2 h2 = *(const float2*)(g_h1 + (unsigned)e2.x * F1 + 2 * f2);
        float2 h3 = *(const float2*)(g_h1 + (unsigned)e3.x * F1 + 2 * f2);
        float w0 = __int_as_float(e0.y), w1 = __int_as_float(e1.y);
        float w2 = __int_as_float(e2.y), w3 = __int_as_float(e3.y);
        ax0 += w0 * h0.x; ay0 += w0 * h0.y;
        ax1 += w1 * h1.x; ay1 += w1 * h1.y;
        ax0 += w2 * h2.x; ay0 += w2 * h2.y;
        ax1 += w3 * h3.x; ay1 += w3 * h3.y;
    }
    for (; i < end; i += 2) {
        int2 e0 = g_cedge[i];
        float2 h0 = *(const float2*)(g_h1 + (unsigned)e0.x * F1 + 2 * f2);
        float w0 = __int_as_float(e0.y);
        ax0 += w0 * h0.x; ay0 += w0 * h0.y;
    }
    float ax = ax0 + ax1, ay = ay0 + ay1;
    ax += __shfl_down_sync(FULL, ax, 16);
    ay += __shfl_down_sync(FULL, ay, 16);
    float di = g_dinv[n];
    float d2 = di * di;
    float2 hs = *(const float2*)(g_h1 + (unsigned)n * F1 + 2 * f2);
    float x1 = ax + d2 * hs.x + b1[2 * f2];
    float y1 = ay + d2 * hs.y + b1[2 * f2 + 1];
    if (lane < 16)
        *(float2*)(g_hrelu + (unsigned)n * F1 + 2 * f2) =
            make_float2(fmaxf(x1, 0.f), fmaxf(y1, 0.f));
}

// h2 = hrelu @ W2 thread-per-node, FFMA2 with LDS.128
__global__ void k_gemm2(const float* __restrict__ W2) {
    __shared__ __align__(16) float sW[F1 * F2];   // 2 KB
    int tid = threadIdx.x;
    for (int i = tid; i < F1 * F2; i += blockDim.x) sW[i] = W2[i];
    __syncthreads();
    int n = blockIdx.x * blockDim.x + tid;
    if (n >= NN) return;
    ull acc[F2 / 2];
#pragma unroll
    for (int j = 0; j < F2 / 2; j++) acc[j] = 0ull;
    const float4* hr = (const float4*)(g_hrelu + (size_t)n * F1);
    const float4* sW4 = (const float4*)sW;
#pragma unroll
    for (int k4 = 0; k4 < F1 / 4; k4++) {
        float4 hv = hr[k4];
        float hs[4] = {hv.x, hv.y, hv.z, hv.w};
#pragma unroll
        for (int kk = 0; kk < 4; kk++) {
            ull hp = pack2(hs[kk], hs[kk]);
            const float4* wrow = sW4 + (k4 * 4 + kk) * (F2 / 4);
#pragma unroll
            for (int j4 = 0; j4 < F2 / 4; j4++) {
                float4 w = wrow[j4];
                acc[2 * j4]     = fma2(hp, pack2(w.x, w.y), acc[2 * j4]);
                acc[2 * j4 + 1] = fma2(hp, pack2(w.z, w.w), acc[2 * j4 + 1]);
            }
        }
    }
    float2* o = (float2*)(g_h2 + (size_t)n * F2);
#pragma unroll
    for (int j = 0; j < F2 / 2; j++) o[j] = unpack2(acc[j]);
}

// layer2 aggregation + FC head + tail zeroing; warp-per-node, QUARTER-warp per edge.
__global__ void k_agg2_final(const float* __restrict__ b2,
                             const float* __restrict__ fc1_w, const float* __restrict__ fc1_b,
                             const float* __restrict__ fc2_w, const float* __restrict__ fc2_b,
                             float* __restrict__ out) {
    const unsigned FULL = 0xffffffffu;
    int lane = threadIdx.x & 31;
    int n = blockIdx.x * (blockDim.x >> 5) + (threadIdx.x >> 5);
    if (n >= NN) return;
    int qtr = lane >> 3;
    int f2 = lane & 7;
    int beg = g_row[n];
    int cnt = g_cnt[n];
    int end = beg + cnt;
    float ax0 = 0.f, ay0 = 0.f, ax1 = 0.f, ay1 = 0.f;
    int i = beg + qtr;
    for (; i + 4 < end; i += 8) {
        int2 e0 = g_cedge[i + 0];
        int2 e1 = g_cedge[i + 4];
        float2 h0 = *(const float2*)(g_h2 + (unsigned)e0.x * F2 + 2 * f2);
        float2 h1 = *(const float2*)(g_h2 + (unsigned)e1.x * F2 + 2 * f2);
        float w0 = __int_as_float(e0.y), w1 = __int_as_float(e1.y);
        ax0 += w0 * h0.x; ay0 += w0 * h0.y;
        ax1 += w1 * h1.x; ay1 += w1 * h1.y;
    }
    for (; i < end; i += 4) {
        int2 e0 = g_cedge[i];
        float2 h0 = *(const float2*)(g_h2 + (unsigned)e0.x * F2 + 2 * f2);
        float w0 = __int_as_float(e0.y);
        ax0 += w0 * h0.x; ay0 += w0 * h0.y;
    }
    float ax = ax0 + ax1, ay = ay0 + ay1;
    ax += __shfl_down_sync(FULL, ax, 16);
    ay += __shfl_down_sync(FULL, ay, 16);
    ax += __shfl_down_sync(FULL, ax, 8);
    ay += __shfl_down_sync(FULL, ay, 8);      // lanes 0..7 hold full sums
    float di = g_dinv[n];
    float d2 = di * di;
    float2 hs = *(const float2*)(g_h2 + (unsigned)n * F2 + 2 * f2);
    float x2x = ax + d2 * hs.x + b2[2 * f2];
    float x2y = ay + d2 * hs.y + b2[2 * f2 + 1];
    float p = x2x * fc1_w[2 * f2] + x2y * fc1_w[2 * f2 + 1];
    p += __shfl_xor_sync(FULL, p, 4);
    p += __shfl_xor_sync(FULL, p, 2);
    p += __shfl_xor_sync(FULL, p, 1);         // lanes 0..7 correct
    float x1f = p + fc1_b[0];
    float c = 1.0f / (1.0f + expf(-x1f));
    float qv = g_hrelu[(unsigned)n * F1 + lane] * fc2_w[lane];
#pragma unroll
    for (int off = 16; off >= 1; off >>= 1) qv += __shfl_xor_sync(FULL, qv, off);
    float r = qv + c * fc2_w[32] + fc2_b[0];
    if (lane == 0) {
        out[n] = r;
        out[NN + n] = x1f;
    }
    // tail zeroing for the NEXT replay (values already consumed above)
    if (lane == 1) g_cnt[n] = 0;
    if (lane == 2) g_dinv[n] = 0.0f;
    if (n == 0 && lane == 3) g_total = 0;
}

// ---------------- launch ----------------
extern "C" void kernel_launch(void* const* d_in, const int* in_sizes, int n_in,
                              void* d_out, int out_size) {
    const float* x     = (const float*)d_in[0];
    const int*   ei    = (const int*)  d_in[1];
    const float* ew    = (const float*)d_in[2];
    const float* W1    = (const float*)d_in[3];
    const float* b1    = (const float*)d_in[4];
    const float* W2    = (const float*)d_in[5];
    const float* b2    = (const float*)d_in[6];
    const float* fc1w  = (const float*)d_in[7];
    const float* fc1b  = (const float*)d_in[8];
    const float* fc2w  = (const float*)d_in[9];
    const float* fc2b  = (const float*)d_in[10];
    float* out = (float*)d_out;

    const int TB = 256;
    const int gW = (NN * 32 + TB - 1) / TB;   // warp-per-node: 8 nodes/block
    (void)in_sizes; (void)n_in; (void)out_size;

    k_gemm1_count<<<G1_BLOCKS + E4_BLOCKS, TB>>>(x, W1, ei, ew);   // 1
    k_scanA<<<NB, 256>>>();                                        // 2
    k_scatter<<<E4_BLOCKS, TB>>>(ei, ew);                          // 3
    k_agg1<<<gW, TB>>>(b1);                                        // 4 -> profiled slot
    k_gemm2<<<NB, TB>>>(W2);                                       // 5
    k_agg2_final<<<gW, TB>>>(b2, fc1w, fc1b, fc2w, fc2b, out);     // 6
}

// round 10
// speedup vs baseline: 1.0848x; 1.0755x over previous
#include <cuda_runtime.h>
#include <math.h>

#define NN 100000
#define NE 3200000
#define INF_ 128
#define F1 32
#define F2 16

typedef unsigned long long ull;

// ---------------- scratch (static device globals; zero-init at module load) ----------------
__device__ float g_dinv[NN];          // weighted-deg accumulator -> rsqrt(deg+1)
__device__ int   g_cnt[NN];           // in-degree counts (persist through aggs)
__device__ int   g_row[NN];           // CSR row start (arrival-order block offsets)
__device__ int   g_cur[NN];           // scatter cursors
__device__ int2  g_cedge[NE];         // (src, norm-as-int-bits) per CSR slot
__device__ float g_h1[NN * F1];       // x @ W1
__device__ float g_hrelu[NN * F1];    // relu(layer1 out)
__device__ float g_h2[NN * F2];       // hrelu @ W2
__device__ int   g_total;             // running block-offset counter (reset in tail)

#define NB 391                        // node blocks of 256 (also gemm1 tile blocks)
#define E4_BLOCKS 3125                // edge blocks (256 thr, 4 edges/thr)

// ---------------- f32x2 packed-FMA helpers (sm_103a FFMA2) ----------------
__device__ __forceinline__ ull pack2(float a, float b) {
    ull r; asm("mov.b64 %0, {%1, %2};" : "=l"(r) : "f"(a), "f"(b)); return r;
}
__device__ __forceinline__ ull fma2(ull a, ull b, ull c) {
    ull d; asm("fma.rn.f32x2 %0, %1, %2, %3;" : "=l"(d) : "l"(a), "l"(b), "l"(c)); return d;
}
__device__ __forceinline__ float2 unpack2(ull v) {
    float x, y; asm("mov.b64 {%0, %1}, %2;" : "=f"(x), "=f"(y) : "l"(v));
    return make_float2(x, y);
}

// ---------------- fat kernel: tiled gemm1 (bid < NB) + batched count ----------------
// gemm tile: 256 nodes x 32 feats per block; thread = 4 nodes x 8 feats.
// smem: sW[128][32] (16KB) + sX[32][256] transposed x-tile (32KB) = 48KB.
__global__ void __launch_bounds__(256) k_gemm1_count(
        const float* __restrict__ x, const float* __restrict__ W1,
        const int* __restrict__ ei, const float* __restrict__ ew) {
    __shared__ __align__(16) float sW[INF_ * F1];   // [k][f]
    __shared__ __align__(16) float sX[32 * 256];    // [k_local][node_local]
    int bid = blockIdx.x;
    int tid = threadIdx.x;
    if (bid < NB) {
        for (int i = tid; i < INF_ * F1; i += 256) sW[i] = W1[i];
        int nbase = bid * 256;
        int ng = tid >> 2;          // node group 0..63 (4 nodes each)
        int fg = tid & 3;           // feature group 0..3 (8 feats each)
        int f0 = fg * 8;
        ull acc[4][4];
#pragma unroll
        for (int c = 0; c < 4; c++)
#pragma unroll
            for (int p = 0; p < 4; p++) acc[c][p] = 0ull;

        for (int kt = 0; kt < 4; kt++) {
            __syncthreads();        // previous compute done (and W loaded) before re-staging
            // stage x-tile transposed: 256 nodes x 32 k -> sX[k][node]
#pragma unroll
            for (int j = 0; j < 8; j++) {
                int flat = tid * 8 + j;     // 0..2047
                int nl = flat >> 3;         // node local 0..255
                int k4 = flat & 7;          // float4 index 0..7
                int n = nbase + nl;
                float4 v = make_float4(0.f, 0.f, 0.f, 0.f);
                if (n < NN)
                    v = *(const float4*)(x + (size_t)n * INF_ + kt * 32 + k4 * 4);
                sX[(k4 * 4 + 0) * 256 + nl] = v.x;
                sX[(k4 * 4 + 1) * 256 + nl] = v.y;
                sX[(k4 * 4 + 2) * 256 + nl] = v.z;
                sX[(k4 * 4 + 3) * 256 + nl] = v.w;
            }
            __syncthreads();
#pragma unroll
            for (int k = 0; k < 32; k++) {
                float4 xv = *(const float4*)&sX[k * 256 + ng * 4];
                const float4* wr = (const float4*)&sW[(kt * 32 + k) * F1 + f0];
                float4 w0 = wr[0], w1 = wr[1];
                ull wp0 = pack2(w0.x, w0.y), wp1 = pack2(w0.z, w0.w);
                ull wp2 = pack2(w1.x, w1.y), wp3 = pack2(w1.z, w1.w);
                float xs[4] = {xv.x, xv.y, xv.z, xv.w};
#pragma unroll
                for (int c = 0; c < 4; c++) {
                    ull xp = pack2(xs[c], xs[c]);
                    acc[c][0] = fma2(xp, wp0, acc[c][0]);
                    acc[c][1] = fma2(xp, wp1, acc[c][1]);
                    acc[c][2] = fma2(xp, wp2, acc[c][2]);
                    acc[c][3] = fma2(xp, wp3, acc[c][3]);
                }
            }
        }
#pragma unroll
        for (int c = 0; c < 4; c++) {
            int n = nbase + ng * 4 + c;
            if (n < NN) {
                float2 v0 = unpack2(acc[c][0]), v1 = unpack2(acc[c][1]);
                float2 v2 = unpack2(acc[c][2]), v3 = unpack2(acc[c][3]);
                float4* o = (float4*)(g_h1 + (size_t)n * F1 + f0);
                o[0] = make_float4(v0.x, v0.y, v1.x, v1.y);
                o[1] = make_float4(v2.x, v2.y, v3.x, v3.y);
            }
        }
    } else {
        // ---- 4 edges per thread: int count + fp weighted degree at dst (REDG) ----
        int e = ((bid - NB) * 256 + tid) * 4;
        if (e >= NE) return;
        int4   d4 = *(const int4*)  (ei + NE + e);
        float4 w4 = *(const float4*)(ew + e);
        atomicAdd(&g_cnt[d4.x], 1);
        atomicAdd(&g_cnt[d4.y], 1);
        atomicAdd(&g_cnt[d4.z], 1);
        atomicAdd(&g_cnt[d4.w], 1);
        atomicAdd(&g_dinv[d4.x], w4.x);
        atomicAdd(&g_dinv[d4.y], w4.y);
        atomicAdd(&g_dinv[d4.z], w4.z);
        atomicAdd(&g_dinv[d4.w], w4.w);
    }
}

// ---- one-kernel scan: block sum -> arrival-order offset -> local exclusive scan ----
__global__ void k_scanA() {
    __shared__ int sh[256];
    __shared__ int s_off;
    int t = threadIdx.x;
    int i = blockIdx.x * 256 + t;
    int v = (i < NN) ? g_cnt[i] : 0;
    sh[t] = v;
    __syncthreads();
    for (int off = 1; off < 256; off <<= 1) {
        int u = (t >= off) ? sh[t - off] : 0;
        __syncthreads();
        sh[t] += u;
        __syncthreads();
    }
    if (t == 255) s_off = atomicAdd(&g_total, sh[255]);
    __syncthreads();
    if (i < NN) {
        int ex = s_off + sh[t] - v;
        g_row[i] = ex;
        g_cur[i] = ex;
        g_dinv[i] = rsqrtf(g_dinv[i] + 1.0f);
    }
}

// 4 edges per thread: norm = dinv[s]*ew*dinv[d]; cursor-atomic scatter into CSR
__global__ void k_scatter(const int* __restrict__ ei, const float* __restrict__ ew) {
    int e = (blockIdx.x * blockDim.x + threadIdx.x) * 4;
    if (e >= NE) return;
    int4   s4 = *(const int4*)  (ei + e);
    int4   d4 = *(const int4*)  (ei + NE + e);
    float4 w4 = *(const float4*)(ew + e);
    float is0 = g_dinv[s4.x], is1 = g_dinv[s4.y], is2 = g_dinv[s4.z], is3 = g_dinv[s4.w];
    float id0 = g_dinv[d4.x], id1 = g_dinv[d4.y], id2 = g_dinv[d4.z], id3 = g_dinv[d4.w];
    float n0 = is0 * w4.x * id0;
    float n1 = is1 * w4.y * id1;
    float n2 = is2 * w4.z * id2;
    float n3 = is3 * w4.w * id3;
    int p0 = atomicAdd(&g_cur[d4.x], 1);
    int p1 = atomicAdd(&g_cur[d4.y], 1);
    int p2 = atomicAdd(&g_cur[d4.z], 1);
    int p3 = atomicAdd(&g_cur[d4.w], 1);
    g_cedge[p0] = make_int2(s4.x, __float_as_int(n0));
    g_cedge[p1] = make_int2(s4.y, __float_as_int(n1));
    g_cedge[p2] = make_int2(s4.z, __float_as_int(n2));
    g_cedge[p3] = make_int2(s4.w, __float_as_int(n3));
}

// layer1 aggregation: warp-per-node, HALF-warp per edge, float2 per lane, unroll 16.
__global__ void k_agg1(const float* __restrict__ b1) {
    const unsigned FULL = 0xffffffffu;
    int lane = threadIdx.x & 31;
    int n = blockIdx.x * (blockDim.x >> 5) + (threadIdx.x >> 5);
    if (n >= NN) return;
    int f2 = lane & 15;
    int half = lane >> 4;
    int beg = g_row[n];
    int end = beg + g_cnt[n];
    float ax0 = 0.f, ay0 = 0.f, ax1 = 0.f, ay1 = 0.f;
    int i = beg + half;
    // 16 edges per iteration (8 per half): loads front-batched for MLP
    for (; i + 14 < end; i += 16) {
        int2 e0 = g_cedge[i + 0];
        int2 e1 = g_cedge[i + 2];
        int2 e2 = g_cedge[i + 4];
        int2 e3 = g_cedge[i + 6];
        int2 e4 = g_cedge[i + 8];
        int2 e5 = g_cedge[i + 10];
        int2 e6 = g_cedge[i + 12];
        int2 e7 = g_cedge[i + 14];
        float2 h0 = *(const float2*)(g_h1 + (unsigned)e0.x * F1 + 2 * f2);
        float2 h1 = *(const float2*)(g_h1 + (unsigned)e1.x * F1 + 2 * f2);
        float2 h2 = *(const float2*)(g_h1 + (unsigned)e2.x * F1 + 2 * f2);
        float2 h3 = *(const float2*)(g_h1 + (unsigned)e3.x * F1 + 2 * f2);
        float2 h4 = *(const float2*)(g_h1 + (unsigned)e4.x * F1 + 2 * f2);
        float2 h5 = *(const float2*)(g_h1 + (unsigned)e5.x * F1 + 2 * f2);
        float2 h6 = *(const float2*)(g_h1 + (unsigned)e6.x * F1 + 2 * f2);
        float2 h7 = *(const float2*)(g_h1 + (unsigned)e7.x * F1 + 2 * f2);
        float w0 = __int_as_float(e0.y), w1 = __int_as_float(e1.y);
        float w2 = __int_as_float(e2.y), w3 = __int_as_float(e3.y);
        float w4 = __int_as_float(e4.y), w5 = __int_as_float(e5.y);
        float w6 = __int_as_float(e6.y), w7 = __int_as_float(e7.y);
        ax0 += w0 * h0.x; ay0 += w0 * h0.y;
        ax1 += w1 * h1.x; ay1 += w1 * h1.y;
        ax0 += w2 * h2.x; ay0 += w2 * h2.y;
        ax1 += w3 * h3.x; ay1 += w3 * h3.y;
        ax0 += w4 * h4.x; ay0 += w4 * h4.y;
        ax1 += w5 * h5.x; ay1 += w5 * h5.y;
        ax0 += w6 * h6.x; ay0 += w6 * h6.y;
        ax1 += w7 * h7.x; ay1 += w7 * h7.y;
    }
    for (; i + 6 < end; i += 8) {
        int2 e0 = g_cedge[i + 0];
        int2 e1 = g_cedge[i + 2];
        int2 e2 = g_cedge[i + 4];
        int2 e3 = g_cedge[i + 6];
        float2 h0 = *(const float2*)(g_h1 + (unsigned)e0.x * F1 + 2 * f2);
        float2 h1 = *(const float2*)(g_h1 + (unsigned)e1.x * F1 + 2 * f2);
        float2 h2 = *(const float2*)(g_h1 + (unsigned)e2.x * F1 + 2 * f2);
        float2 h3 = *(const float2*)(g_h1 + (unsigned)e3.x * F1 + 2 * f2);
        float w0 = __int_as_float(e0.y), w1 = __int_as_float(e1.y);
        float w2 = __int_as_float(e2.y), w3 = __int_as_float(e3.y);
        ax0 += w0 * h0.x; ay0 += w0 * h0.y;
        ax1 += w1 * h1.x; ay1 += w1 * h1.y;
        ax0 += w2 * h2.x; ay0 += w2 * h2.y;
        ax1 += w3 * h3.x; ay1 += w3 * h3.y;
    }
    for (; i < end; i += 2) {
        int2 e0 = g_cedge[i];
        float2 h0 = *(const float2*)(g_h1 + (unsigned)e0.x * F1 + 2 * f2);
        float w0 = __int_as_float(e0.y);
        ax0 += w0 * h0.x; ay0 += w0 * h0.y;
    }
    float ax = ax0 + ax1, ay = ay0 + ay1;
    ax += __shfl_down_sync(FULL, ax, 16);
    ay += __shfl_down_sync(FULL, ay, 16);
    float di = g_dinv[n];
    float d2 = di * di;
    float2 hs = *(const float2*)(g_h1 + (unsigned)n * F1 + 2 * f2);
    float x1 = ax + d2 * hs.x + b1[2 * f2];
    float y1 = ay + d2 * hs.y + b1[2 * f2 + 1];
    if (lane < 16)
        *(float2*)(g_hrelu + (unsigned)n * F1 + 2 * f2) =
            make_float2(fmaxf(x1, 0.f), fmaxf(y1, 0.f));
}

// h2 = hrelu @ W2 thread-per-node, FFMA2 with LDS.128
__global__ void k_gemm2(const float* __restrict__ W2) {
    __shared__ __align__(16) float sW[F1 * F2];   // 2 KB
    int tid = threadIdx.x;
    for (int i = tid; i < F1 * F2; i += blockDim.x) sW[i] = W2[i];
    __syncthreads();
    int n = blockIdx.x * blockDim.x + tid;
    if (n >= NN) return;
    ull acc[F2 / 2];
#pragma unroll
    for (int j = 0; j < F2 / 2; j++) acc[j] = 0ull;
    const float4* hr = (const float4*)(g_hrelu + (size_t)n * F1);
    const float4* sW4 = (const float4*)sW;
#pragma unroll
    for (int k4 = 0; k4 < F1 / 4; k4++) {
        float4 hv = hr[k4];
        float hs[4] = {hv.x, hv.y, hv.z, hv.w};
#pragma unroll
        for (int kk = 0; kk < 4; kk++) {
            ull hp = pack2(hs[kk], hs[kk]);
            const float4* wrow = sW4 + (k4 * 4 + kk) * (F2 / 4);
#pragma unroll
            for (int j4 = 0; j4 < F2 / 4; j4++) {
                float4 w = wrow[j4];
                acc[2 * j4]     = fma2(hp, pack2(w.x, w.y), acc[2 * j4]);
                acc[2 * j4 + 1] = fma2(hp, pack2(w.z, w.w), acc[2 * j4 + 1]);
            }
        }
    }
    float2* o = (float2*)(g_h2 + (size_t)n * F2);
#pragma unroll
    for (int j = 0; j < F2 / 2; j++) o[j] = unpack2(acc[j]);
}

// layer2 aggregation + FC head + tail zeroing; warp-per-node, QUARTER-warp, unroll 16.
__global__ void k_agg2_final(const float* __restrict__ b2,
                             const float* __restrict__ fc1_w, const float* __restrict__ fc1_b,
                             const float* __restrict__ fc2_w, const float* __restrict__ fc2_b,
                             float* __restrict__ out) {
    const unsigned FULL = 0xffffffffu;
    int lane = threadIdx.x & 31;
    int n = blockIdx.x * (blockDim.x >> 5) + (threadIdx.x >> 5);
    if (n >= NN) return;
    int qtr = lane >> 3;
    int f2 = lane & 7;
    int beg = g_row[n];
    int cnt = g_cnt[n];
    int end = beg + cnt;
    float ax0 = 0.f, ay0 = 0.f, ax1 = 0.f, ay1 = 0.f;
    int i = beg + qtr;
    for (; i + 12 < end; i += 16) {
        int2 e0 = g_cedge[i + 0];
        int2 e1 = g_cedge[i + 4];
        int2 e2 = g_cedge[i + 8];
        int2 e3 = g_cedge[i + 12];
        float2 h0 = *(const float2*)(g_h2 + (unsigned)e0.x * F2 + 2 * f2);
        float2 h1 = *(const float2*)(g_h2 + (unsigned)e1.x * F2 + 2 * f2);
        float2 h2 = *(const float2*)(g_h2 + (unsigned)e2.x * F2 + 2 * f2);
        float2 h3 = *(const float2*)(g_h2 + (unsigned)e3.x * F2 + 2 * f2);
        float w0 = __int_as_float(e0.y), w1 = __int_as_float(e1.y);
        float w2 = __int_as_float(e2.y), w3 = __int_as_float(e3.y);
        ax0 += w0 * h0.x; ay0 += w0 * h0.y;
        ax1 += w1 * h1.x; ay1 += w1 * h1.y;
        ax0 += w2 * h2.x; ay0 += w2 * h2.y;
        ax1 += w3 * h3.x; ay1 += w3 * h3.y;
    }
    for (; i < end; i += 4) {
        int2 e0 = g_cedge[i];
        float2 h0 = *(const float2*)(g_h2 + (unsigned)e0.x * F2 + 2 * f2);
        float w0 = __int_as_float(e0.y);
        ax0 += w0 * h0.x; ay0 += w0 * h0.y;
    }
    float ax = ax0 + ax1, ay = ay0 + ay1;
    ax += __shfl_down_sync(FULL, ax, 16);
    ay += __shfl_down_sync(FULL, ay, 16);
    ax += __shfl_down_sync(FULL, ax, 8);
    ay += __shfl_down_sync(FULL, ay, 8);      // lanes 0..7 hold full sums
    float di = g_dinv[n];
    float d2 = di * di;
    float2 hs = *(const float2*)(g_h2 + (unsigned)n * F2 + 2 * f2);
    float x2x = ax + d2 * hs.x + b2[2 * f2];
    float x2y = ay + d2 * hs.y + b2[2 * f2 + 1];
    float p = x2x * fc1_w[2 * f2] + x2y * fc1_w[2 * f2 + 1];
    p += __shfl_xor_sync(FULL, p, 4);
    p += __shfl_xor_sync(FULL, p, 2);
    p += __shfl_xor_sync(FULL, p, 1);         // lanes 0..7 correct
    float x1f = p + fc1_b[0];
    float c = 1.0f / (1.0f + expf(-x1f));
    float qv = g_hrelu[(unsigned)n * F1 + lane] * fc2_w[lane];
#pragma unroll
    for (int off = 16; off >= 1; off >>= 1) qv += __shfl_xor_sync(FULL, qv, off);
    float r = qv + c * fc2_w[32] + fc2_b[0];
    if (lane == 0) {
        out[n] = r;
        out[NN + n] = x1f;
    }
    // tail zeroing for the NEXT replay (values already consumed above)
    if (lane == 1) g_cnt[n] = 0;
    if (lane == 2) g_dinv[n] = 0.0f;
    if (n == 0 && lane == 3) g_total = 0;
}

// ---------------- launch ----------------
extern "C" void kernel_launch(void* const* d_in, const int* in_sizes, int n_in,
                              void* d_out, int out_size) {
    const float* x     = (const float*)d_in[0];
    const int*   ei    = (const int*)  d_in[1];
    const float* ew    = (const float*)d_in[2];
    const float* W1    = (const float*)d_in[3];
    const float* b1    = (const float*)d_in[4];
    const float* W2    = (const float*)d_in[5];
    const float* b2    = (const float*)d_in[6];
    const float* fc1w  = (const float*)d_in[7];
    const float* fc1b  = (const float*)d_in[8];
    const float* fc2w  = (const float*)d_in[9];
    const float* fc2b  = (const float*)d_in[10];
    float* out = (float*)d_out;

    const int TB = 256;
    const int gW = (NN * 32 + TB - 1) / TB;   // warp-per-node: 8 nodes/block
    (void)in_sizes; (void)n_in; (void)out_size;

    k_gemm1_count<<<NB + E4_BLOCKS, TB>>>(x, W1, ei, ew);          // 1
    k_scanA<<<NB, 256>>>();                                        // 2
    k_scatter<<<E4_BLOCKS, TB>>>(ei, ew);                          // 3
    k_agg1<<<gW, TB>>>(b1);                                        // 4 -> profiled slot
    k_gemm2<<<NB, TB>>>(W2);                                       // 5
    k_agg2_final<<<gW, TB>>>(b2, fc1w, fc1b, fc2w, fc2b, out);     // 6
}